// round 16
// baseline (speedup 1.0000x reference)
#include <cuda_runtime.h>
#include <cstdint>

// Residual VQ forward. Bitwise-exact argmin via int8 dp4a prefilter with a
// CERTIFIED quantization-error window. Filter = pure int8 GEMM -> int32
// scratch; select computes minUB = min(d+err), collects certified candidates,
// exact fp32 rescore (bitwise reference chain), update + fused requantize.
// Output: [ quantized (16384*512) | indices as float (16384*8) | loss (1) ]

#define NROWS 16384
#define DIMD  512
#define KSZ   2048
#define NQ    8
#define SBLK  2048
#define SCAP  64
#define FBM   64

__device__ float    g_residual[NROWS * DIMD];
__device__ float    g_cnorm[NQ * KSZ];
__device__ float    g_a[NROWS];
__device__ double   g_lpart[NQ * SBLK];
__device__ uint32_t g_ri8[NROWS * (DIMD / 4)];
__device__ uint32_t g_ci8[NQ * KSZ * (DIMD / 4)];
__device__ float    g_sr[NROWS];
__device__ float    g_l1r[NROWS];
__device__ float    g_sc[NQ * KSZ];
__device__ float    g_scu[NQ * KSZ];    // u_k = s_c*(0.5*L1c + 128)
__device__ float    g_scv[NQ * KSZ];    // v_k = 0.5*s_c
__device__ int      g_sgi[NROWS * KSZ]; // raw int32 dp scores (128 MB)

__device__ __forceinline__ int dp4a_s(uint32_t a, uint32_t b, int c) {
    return __dp4a((int)a, (int)b, c);
}

// ---------------- exact-numerics helpers (bitwise = reference) -------------
__device__ __forceinline__ float sq_norm_16lane(const float* __restrict__ p) {
    float S[16];
#pragma unroll
    for (int l = 0; l < 16; l++) S[l] = 0.f;
#pragma unroll 4
    for (int j = 0; j < 32; j++) {
        const float4* q = (const float4*)(p + j * 16);
        float4 v0 = q[0], v1 = q[1], v2 = q[2], v3 = q[3];
        S[0]  = fmaf(v0.x, v0.x, S[0]);  S[1]  = fmaf(v0.y, v0.y, S[1]);
        S[2]  = fmaf(v0.z, v0.z, S[2]);  S[3]  = fmaf(v0.w, v0.w, S[3]);
        S[4]  = fmaf(v1.x, v1.x, S[4]);  S[5]  = fmaf(v1.y, v1.y, S[5]);
        S[6]  = fmaf(v1.z, v1.z, S[6]);  S[7]  = fmaf(v1.w, v1.w, S[7]);
        S[8]  = fmaf(v2.x, v2.x, S[8]);  S[9]  = fmaf(v2.y, v2.y, S[9]);
        S[10] = fmaf(v2.z, v2.z, S[10]); S[11] = fmaf(v2.w, v2.w, S[11]);
        S[12] = fmaf(v3.x, v3.x, S[12]); S[13] = fmaf(v3.y, v3.y, S[13]);
        S[14] = fmaf(v3.z, v3.z, S[14]); S[15] = fmaf(v3.w, v3.w, S[15]);
    }
    float u0 = (S[0] + S[4]) + (S[8]  + S[12]);
    float u1 = (S[1] + S[5]) + (S[9]  + S[13]);
    float u2 = (S[2] + S[6]) + (S[10] + S[14]);
    float u3 = (S[3] + S[7]) + (S[11] + S[15]);
    return (u0 + u1) + (u2 + u3);
}

__device__ __forceinline__ int q8(float v, float inv) {
    int q = __float2int_rn(v * inv);
    return max(-127, min(127, q));
}

// quantize one fp32 row of 512 to int8 (per-row scale) + L1 norm; warp/row
__device__ __forceinline__ void quant_row(const float* __restrict__ src,
                                          uint32_t* __restrict__ dst8,
                                          int lane, float* outS, int* outL1) {
    const float4* s4 = (const float4*)src;
    float4 v[4];
#pragma unroll
    for (int j = 0; j < 4; j++) v[j] = s4[j * 32 + lane];
    float mx = 0.f;
#pragma unroll
    for (int j = 0; j < 4; j++) {
        mx = fmaxf(mx, fmaxf(fmaxf(fabsf(v[j].x), fabsf(v[j].y)),
                             fmaxf(fabsf(v[j].z), fabsf(v[j].w))));
    }
#pragma unroll
    for (int o = 16; o > 0; o >>= 1)
        mx = fmaxf(mx, __shfl_xor_sync(0xffffffffu, mx, o));
    float mxa = fmaxf(mx, 1e-30f);
    float s = mxa / 127.f;
    float inv = 127.f / mxa;
    int L1 = 0;
#pragma unroll
    for (int j = 0; j < 4; j++) {
        int q0 = q8(v[j].x, inv), q1 = q8(v[j].y, inv);
        int q2 = q8(v[j].z, inv), q3 = q8(v[j].w, inv);
        L1 += abs(q0) + abs(q1) + abs(q2) + abs(q3);
        uint32_t pk = (uint32_t)(q0 & 255) | ((uint32_t)(q1 & 255) << 8)
                    | ((uint32_t)(q2 & 255) << 16) | ((uint32_t)(q3 & 255) << 24);
        dst8[j * 32 + lane] = pk;
    }
#pragma unroll
    for (int o = 16; o > 0; o >>= 1)
        L1 += __shfl_xor_sync(0xffffffffu, L1, o);
    *outS = s; *outL1 = L1;
}

// ---------------- setup kernels --------------------------------------------
__global__ void rvq_init(const float4* __restrict__ x, float4* __restrict__ outQ) {
    int i = blockIdx.x * blockDim.x + threadIdx.x;
    if (i < NROWS * DIMD / 4) {
        ((float4*)g_residual)[i] = x[i];
        outQ[i] = make_float4(0.f, 0.f, 0.f, 0.f);
    }
}
__global__ void rvq_qcode(const float* __restrict__ cb) {   // grid 2048 x 256
    int wid = threadIdx.x >> 5, lane = threadIdx.x & 31;
    int cr = blockIdx.x * 8 + wid;
    float s; int L1;
    quant_row(cb + (long long)cr * DIMD, g_ci8 + (long long)cr * 128, lane, &s, &L1);
    if (lane == 0) {
        g_sc[cr]  = s;
        g_scu[cr] = s * (0.5f * (float)L1 + 128.f);
        g_scv[cr] = 0.5f * s;
    }
}
__global__ void rvq_cnorm(const float* __restrict__ cb) {
    int r = blockIdx.x * blockDim.x + threadIdx.x;
    if (r < NQ * KSZ) g_cnorm[r] = sq_norm_16lane(cb + (long long)r * DIMD);
}
__global__ void rvq_norm0() {
    int row = blockIdx.x * blockDim.x + threadIdx.x;
    if (row < NROWS) g_a[row] = sq_norm_16lane(g_residual + (long long)row * DIMD);
}
__global__ void rvq_qres() {                                // grid 2048 x 256
    int wid = threadIdx.x >> 5, lane = threadIdx.x & 31;
    int row = blockIdx.x * 8 + wid;
    float s; int L1;
    quant_row(g_residual + (long long)row * DIMD, g_ri8 + (long long)row * 128,
              lane, &s, &L1);
    if (lane == 0) { g_sr[row] = s; g_l1r[row] = (float)L1; }
}

// ---------------- pure dp4a GEMM (phase 1) ---------------------------------
// 64 rows x 2048 codes per CTA; grid 256; 2 CTAs/SM (13 KB smem).
__global__ void __launch_bounds__(256)
rvq_filter(int level)
{
    __shared__ uint32_t As[2][8][68];
    __shared__ uint32_t Bs[2][8][132];

    const int tid = threadIdx.x;
    const int tx = tid & 15, ty = tid >> 4;
    const int rowBase = blockIdx.x * FBM;
    const bool aldr = tid < 128;
    const int ar = tid >> 1;            // A row (0..63) when aldr
    const int ap = tid & 1;             // A word-part
    const int br = tid >> 1;            // B row (0..127)
    const int bp = tid & 1;

    const uint32_t* __restrict__ Ai = g_ri8 + (long long)rowBase * 128;
    const uint32_t* __restrict__ Bi = g_ci8 + (long long)level * KSZ * 128;

    uint4 pa, pb;
    {   // t = 0 into stage 0
        if (aldr) {
            uint4 a0 = *(const uint4*)&Ai[ar * 128 + ap * 4];
            As[0][ap * 4 + 0][ar] = a0.x; As[0][ap * 4 + 1][ar] = a0.y;
            As[0][ap * 4 + 2][ar] = a0.z; As[0][ap * 4 + 3][ar] = a0.w;
        }
        uint4 b0 = *(const uint4*)&Bi[br * 128 + bp * 4];
        Bs[0][bp * 4 + 0][br] = b0.x; Bs[0][bp * 4 + 1][br] = b0.y;
        Bs[0][bp * 4 + 2][br] = b0.z; Bs[0][bp * 4 + 3][br] = b0.w;
        // prefetch t = 1 (chunk 0, step 1)
        if (aldr) pa = *(const uint4*)&Ai[ar * 128 + 8 + ap * 4];
        pb = *(const uint4*)&Bi[br * 128 + 8 + bp * 4];
    }

    int acc[4][8];
    const int TOT = 256;   // 16 n-chunks x 16 k-steps
    for (int t = 0; t < TOT; t++) {
        const int ds = t & 15, buf = t & 1;
        if (ds == 0) {
#pragma unroll
            for (int m = 0; m < 4; m++)
#pragma unroll
                for (int n = 0; n < 8; n++) acc[m][n] = 0;
        }
        __syncthreads();
        if (t + 1 < TOT) {
            const int nb = buf ^ 1;
            if (aldr) {
                As[nb][ap * 4 + 0][ar] = pa.x; As[nb][ap * 4 + 1][ar] = pa.y;
                As[nb][ap * 4 + 2][ar] = pa.z; As[nb][ap * 4 + 3][ar] = pa.w;
            }
            Bs[nb][bp * 4 + 0][br] = pb.x; Bs[nb][bp * 4 + 1][br] = pb.y;
            Bs[nb][bp * 4 + 2][br] = pb.z; Bs[nb][bp * 4 + 3][br] = pb.w;
        }
        if (t + 2 < TOT) {
            int s2 = t + 2, nn = s2 >> 4, stp = s2 & 15;
            if (aldr) pa = *(const uint4*)&Ai[ar * 128 + stp * 8 + ap * 4];
            pb = *(const uint4*)&Bi[(long long)(nn * 128 + br) * 128 + stp * 8 + bp * 4];
        }
#pragma unroll
        for (int k4 = 0; k4 < 8; k4++) {
            uint32_t af[4], bf[8];
            *(uint4*)&af[0] = *(const uint4*)&As[buf][k4][ty * 4];
            *(uint4*)&bf[0] = *(const uint4*)&Bs[buf][k4][tx * 8];
            *(uint4*)&bf[4] = *(const uint4*)&Bs[buf][k4][tx * 8 + 4];
#pragma unroll
            for (int m = 0; m < 4; m++)
#pragma unroll
                for (int n = 0; n < 8; n++)
                    acc[m][n] = dp4a_s(af[m], bf[n], acc[m][n]);
        }
        if (ds == 15) {
            const int nc = t >> 4;
#pragma unroll
            for (int m = 0; m < 4; m++) {
                int* dst = g_sgi + (long long)(rowBase + ty * 4 + m) * KSZ
                         + nc * 128 + tx * 8;
                *(int4*)dst       = make_int4(acc[m][0], acc[m][1], acc[m][2], acc[m][3]);
                *(int4*)(dst + 4) = make_int4(acc[m][4], acc[m][5], acc[m][6], acc[m][7]);
            }
        }
    }
}

// ---------------- select: minUB + collect + exact rescore + update ---------
// dyn smem: stage 8w x 4r x 516 f = 66048 ; rs 8x512 f = 16384 ;
//           ck 8x64 i = 2048 ; cN 8 i = 32 ; wpart 8 d = 64
#define SEL_RESS  66048
#define SEL_CK    82432
#define SEL_CN    84480
#define SEL_WP    84512
#define SEL_TOT   84576

__global__ void __launch_bounds__(256)
rvq_select(const float* __restrict__ cb, float* __restrict__ outQ,
           float* __restrict__ outIdx, int level)
{
    extern __shared__ __align__(16) char smem[];
    const int tid = threadIdx.x, wid = tid >> 5, lane = tid & 31;
    float*  stg0  = (float*)smem + wid * (4 * 516);
    float*  rs    = (float*)(smem + SEL_RESS) + wid * 512;
    int*    ck    = (int*)(smem + SEL_CK) + wid * SCAP;
    int*    cN    = (int*)(smem + SEL_CN);
    double* wpart = (double*)(smem + SEL_WP);

    const int row = blockIdx.x * 8 + wid;
    float* res = g_residual + (long long)row * DIMD;
    const float* __restrict__ cnm = g_cnorm + level * KSZ;
    const float* __restrict__ scA = g_sc  + level * KSZ;
    const float* __restrict__ suA = g_scu + level * KSZ;
    const float* __restrict__ svA = g_scv + level * KSZ;
    const int4* __restrict__ sgi4 = (const int4*)(g_sgi + (long long)row * KSZ);

    const float aR  = g_a[row];
    const float srR = g_sr[row];
    const float l1r = g_l1r[row];
    const float c2n = -2.f * srR;
    const float c2e =  2.f * srR;

    if (lane == 0) cN[wid] = 0;
    {   // residual row to smem (coalesced)
        const float4* s4 = (const float4*)res;
        float4* d4 = (float4*)rs;
#pragma unroll
        for (int i = 0; i < 4; i++) d4[lane + i * 32] = s4[lane + i * 32];
    }

    // pass 1: minUB = min_k (d_k + err_k)  -- certified upper bound on exact min
    float mUB = 3.4e38f;
#pragma unroll 4
    for (int i = 0; i < 16; i++) {
        int i4 = lane + i * 32;
        int4 dp = sgi4[i4];
        int k0 = i4 * 4;
        float4 sc = *(const float4*)(scA + k0);
        float4 cn = *(const float4*)(cnm + k0);
        float4 su = *(const float4*)(suA + k0);
        float4 sv = *(const float4*)(svA + k0);
        float d0 = fmaf(c2n * sc.x, (float)dp.x, aR) + cn.x;
        float d1 = fmaf(c2n * sc.y, (float)dp.y, aR) + cn.y;
        float d2 = fmaf(c2n * sc.z, (float)dp.z, aR) + cn.z;
        float d3 = fmaf(c2n * sc.w, (float)dp.w, aR) + cn.w;
        float e0 = c2e * fmaf(sv.x, l1r, su.x);
        float e1 = c2e * fmaf(sv.y, l1r, su.y);
        float e2 = c2e * fmaf(sv.z, l1r, su.z);
        float e3 = c2e * fmaf(sv.w, l1r, su.w);
        mUB = fminf(mUB, fminf(fminf(d0 + e0, d1 + e1), fminf(d2 + e2, d3 + e3)));
    }
#pragma unroll
    for (int o = 16; o > 0; o >>= 1)
        mUB = fminf(mUB, __shfl_xor_sync(0xffffffffu, mUB, o));
    const float thrBase = mUB + 6e-4f;

    // pass 2: collect candidates with d_k <= thrBase + err_k
#pragma unroll 4
    for (int i = 0; i < 16; i++) {
        int i4 = lane + i * 32;
        int4 dp = sgi4[i4];
        int k0 = i4 * 4;
        float4 sc = *(const float4*)(scA + k0);
        float4 cn = *(const float4*)(cnm + k0);
        float4 su = *(const float4*)(suA + k0);
        float4 sv = *(const float4*)(svA + k0);
        float d0 = fmaf(c2n * sc.x, (float)dp.x, aR) + cn.x;
        float d1 = fmaf(c2n * sc.y, (float)dp.y, aR) + cn.y;
        float d2 = fmaf(c2n * sc.z, (float)dp.z, aR) + cn.z;
        float d3 = fmaf(c2n * sc.w, (float)dp.w, aR) + cn.w;
        float e0 = c2e * fmaf(sv.x, l1r, su.x);
        float e1 = c2e * fmaf(sv.y, l1r, su.y);
        float e2 = c2e * fmaf(sv.z, l1r, su.z);
        float e3 = c2e * fmaf(sv.w, l1r, su.w);
        if (d0 <= thrBase + e0) { int p = atomicAdd(&cN[wid], 1); if (p < SCAP) ck[p] = k0; }
        if (d1 <= thrBase + e1) { int p = atomicAdd(&cN[wid], 1); if (p < SCAP) ck[p] = k0 + 1; }
        if (d2 <= thrBase + e2) { int p = atomicAdd(&cN[wid], 1); if (p < SCAP) ck[p] = k0 + 2; }
        if (d3 <= thrBase + e3) { int p = atomicAdd(&cN[wid], 1); if (p < SCAP) ck[p] = k0 + 3; }
    }
    __syncwarp();
    const int n = cN[wid];

    float bd = 3.4e38f; int bk = KSZ;
    if (n <= SCAP) {
        for (int base = 0; base < n; base += 4) {
            int nb = min(4, n - base);
            for (int r = 0; r < nb; r++) {   // coalesced stage of candidate rows
                const float4* src = (const float4*)(cb + (long long)ck[base + r] * DIMD);
                float4* dstp = (float4*)(stg0 + r * 516);
#pragma unroll
                for (int i = 0; i < 4; i++) dstp[lane + i * 32] = src[lane + i * 32];
            }
            __syncwarp();
            if (lane < nb) {   // bitwise-exact sequential chain from smem
                int k = ck[base + lane];
                const float* crow = stg0 + lane * 516;
                float e = 0.f;
#pragma unroll 8
                for (int d = 0; d < DIMD; d++) e = fmaf(rs[d], crow[d], e);
                float tt = fmaf(-2.f, e, aR);
                float dd = tt + cnm[k];
                if (dd < bd || (dd == bd && k < bk)) { bd = dd; bk = k; }
            }
            __syncwarp();
        }
    } else {
        // safety net (never expected): exact rescore of ALL codes, staged
        for (int base = 0; base < KSZ; base += 4) {
            for (int r = 0; r < 4; r++) {
                const float4* src = (const float4*)(cb + (long long)(base + r) * DIMD);
                float4* dstp = (float4*)(stg0 + r * 516);
#pragma unroll
                for (int i = 0; i < 4; i++) dstp[lane + i * 32] = src[lane + i * 32];
            }
            __syncwarp();
            if (lane < 4) {
                int k = base + lane;
                const float* crow = stg0 + lane * 516;
                float e = 0.f;
#pragma unroll 8
                for (int d = 0; d < DIMD; d++) e = fmaf(rs[d], crow[d], e);
                float tt = fmaf(-2.f, e, aR);
                float dd = tt + cnm[k];
                if (dd < bd || (dd == bd && k < bk)) { bd = dd; bk = k; }
            }
            __syncwarp();
        }
    }
    // warp reduce lexicographic (min d, then min k)
#pragma unroll
    for (int o = 16; o > 0; o >>= 1) {
        float d2 = __shfl_down_sync(0xffffffffu, bd, o);
        int   k2 = __shfl_down_sync(0xffffffffu, bk, o);
        if (d2 < bd || (d2 == bd && k2 < bk)) { bd = d2; bk = k2; }
    }
    const int bestK = __shfl_sync(0xffffffffu, bk, 0);
    if (lane == 0 && outIdx) outIdx[(long long)row * NQ + level] = (float)bestK;

    // update: res -= q ; outQ += q ; loss partial ; rs mirrors new residual
    const float* __restrict__ q = cb + (long long)bestK * DIMD;
    float* oq = outQ + (long long)row * DIMD;
    double ls = 0.0;
    for (int e = lane; e < DIMD; e += 32) {
        float qq = q[e];
        float rv = res[e] - qq;
        res[e] = rv;
        rs[e] = rv;
        oq[e] += qq;
        ls += (double)rv * rv;
    }
    __syncwarp();
    // exact 16-lane row norm of the new residual (bitwise = reference)
    float S = 0.f;
    if (lane < 16) {
        for (int j = 0; j < 32; j++) { float v = rs[16 * j + lane]; S = fmaf(v, v, S); }
    }
    float t1 = S + __shfl_down_sync(0xffffffffu, S, 4);
    float u  = t1 + __shfl_down_sync(0xffffffffu, t1, 8);
    float v2 = u + __shfl_down_sync(0xffffffffu, u, 1);
    float an = v2 + __shfl_down_sync(0xffffffffu, v2, 2);
    if (lane == 0) g_a[row] = an;
    // fused requantize of the new residual for the next level's filter
    {
        float s; int L1;
        quant_row(rs, g_ri8 + (long long)row * 128, lane, &s, &L1);
        if (lane == 0) { g_sr[row] = s; g_l1r[row] = (float)L1; }
    }
#pragma unroll
    for (int o = 16; o > 0; o >>= 1) ls += __shfl_down_sync(0xffffffffu, ls, o);
    if (lane == 0) wpart[wid] = ls;
    __syncthreads();
    if (tid == 0) {
        double t = 0.0;
        for (int w = 0; w < 8; w++) t += wpart[w];
        g_lpart[level * SBLK + blockIdx.x] = t;
    }
}

// ---------------- epilogues ------------------------------------------------
__global__ void rvq_ste(const float* __restrict__ x, float* __restrict__ outQ) {
    int i = blockIdx.x * blockDim.x + threadIdx.x;
    if (i < NROWS * DIMD) {
        float xv = x[i];
        float qv = outQ[i];
        outQ[i] = xv + (qv - xv);
    }
}
__global__ void rvq_finalize(float* __restrict__ outLoss) {
    __shared__ double red[256];
    int tid = threadIdx.x;
    double t = 0.0;
    for (int i = tid; i < NQ * SBLK; i += 256) t += g_lpart[i];
    red[tid] = t; __syncthreads();
    for (int o = 128; o > 0; o >>= 1) {
        if (tid < o) red[tid] += red[tid + o];
        __syncthreads();
    }
    if (tid == 0) {
        double denom = 8.0 * (double)NROWS * (double)DIMD;
        *outLoss = (float)(red[0] * 1.25 / denom);
    }
}

// ---------------------------------------------------------------------------
extern "C" void kernel_launch(void* const* d_in, const int* in_sizes, int n_in,
                              void* d_out, int out_size) {
    const float* x  = (const float*)d_in[0];
    const float* cb = (const float*)d_in[1];
    float* out = (float*)d_out;
    float* outQ = out;
    float* outIdx = (out_size >= NROWS * DIMD + NROWS * NQ) ? (out + NROWS * DIMD)
                                                            : (float*)0;

    cudaFuncSetAttribute(rvq_select, cudaFuncAttributeMaxDynamicSharedMemorySize,
                         SEL_TOT);

    // launch order chosen so the 6th launch is rvq_filter (ncu -s 5 -c 1)
    rvq_init<<<(NROWS * DIMD / 4 + 255) / 256, 256>>>((const float4*)x, (float4*)outQ);
    rvq_qcode<<<NQ * KSZ / 8, 256>>>(cb);
    rvq_cnorm<<<(NQ * KSZ + 255) / 256, 256>>>(cb);
    rvq_norm0<<<(NROWS + 255) / 256, 256>>>();
    rvq_qres<<<NROWS / 8, 256>>>();

    for (int l = 0; l < NQ; l++) {
        rvq_filter<<<NROWS / FBM, 256>>>(l);
        rvq_select<<<SBLK, 256, SEL_TOT>>>(cb + (long long)l * KSZ * DIMD,
                                           outQ, outIdx, l);
    }

    rvq_ste<<<(NROWS * DIMD + 255) / 256, 256>>>(x, outQ);
    if (out_size >= NROWS * DIMD + NROWS * NQ + 1) {
        rvq_finalize<<<1, 256>>>(out + NROWS * DIMD + NROWS * NQ);
    }
}